// round 13
// baseline (speedup 1.0000x reference)
#include <cuda_runtime.h>
#include <math.h>

#define NN 768
#define CNT 767.0f
#define NT 24
#define GRID 600
#define TPB 256

typedef unsigned long long ull;

__device__ __align__(16) float g_embed0[NN*32];
__device__ __align__(16) float g_acc1[NN*32];
__device__ __align__(16) float g_e1[NN*64];
__device__ __align__(16) float g_acc2[NN*32];
__device__ float g_aggsum[160];
__device__ unsigned g_bar;
__device__ __align__(16) float g_B1t[16*NN*2];
__device__ __align__(16) float g_P1t[16*NN*2];
__device__ __align__(16) float g_B2t[16*NN*2];
__device__ __align__(16) float g_P2t[16*NN*2];

__constant__ __align__(16) float cWe[2][32*32];

__device__ __forceinline__ float silu_f(float x) {
    return __fdividef(x, 1.0f + __expf(-x));
}
__device__ __forceinline__ float silu_t(float x) {
    float xh = 0.5f * x, t;
    asm("tanh.approx.f32 %0, %1;" : "=f"(t) : "f"(xh));
    return fmaf(xh, t, xh);
}
__device__ __forceinline__ ull pk2(float lo, float hi) {
    ull r; asm("mov.b64 %0, {%1,%2};" : "=l"(r) : "f"(lo), "f"(hi)); return r;
}
__device__ __forceinline__ void upk2(ull v, float& lo, float& hi) {
    asm("mov.b64 {%0,%1}, %2;" : "=f"(lo), "=f"(hi) : "l"(v));
}
__device__ __forceinline__ ull fma2(ull a, ull b, ull c) {
    ull d; asm("fma.rn.f32x2 %0, %1, %2, %3;" : "=l"(d) : "l"(a), "l"(b), "l"(c)); return d;
}
__device__ __forceinline__ ull add2(ull a, ull b) {
    ull d; asm("add.rn.f32x2 %0, %1, %2;" : "=l"(d) : "l"(a), "l"(b)); return d;
}

// grid-wide barrier: all blocks co-resident (guaranteed by launch config check)
__device__ __forceinline__ void gridsync(unsigned target) {
    __threadfence();                      // publish this thread's writes (gpu scope)
    __syncthreads();
    if (threadIdx.x == 0) {
        atomicAdd(&g_bar, 1u);
        unsigned v, spin = 0;
        do {
            asm volatile("ld.global.acquire.gpu.u32 %0, [%1];" : "=r"(v) : "l"(&g_bar) : "memory");
            if (++spin > (1u << 24)) break;            // hang guard
            if (v < target) __nanosleep(64);
        } while (v < target);
        __threadfence();                  // CCTL.IVALL: fresh L1 for this SM
    }
    __syncthreads();
}

// ---------------- phase 0: prep ----------------
__device__ __forceinline__ void prep_phase(const float* __restrict__ embed_table,
                                           const int*   __restrict__ charges,
                                           const float* __restrict__ mp1_w0,
                                           const float* __restrict__ mp1_b0)
{
    int gid = blockIdx.x * TPB + threadIdx.x;
    if (gid >= NN*32) return;
    int n = gid >> 5, j = gid & 31;
    int c = __ldg(&charges[n]);
    const float* er = embed_table + c * 32;
    float e0 = __ldg(&er[j]);
    g_embed0[n*32 + j] = e0;
    float a = __ldg(&mp1_b0[j]), b = 0.0f;
    #pragma unroll
    for (int k = 0; k < 32; k++) {
        float e = __ldg(&er[k]);
        a = fmaf(e, __ldg(&mp1_w0[k*32 + j]),        a);
        b = fmaf(e, __ldg(&mp1_w0[(32 + k)*32 + j]), b);
    }
    g_B1t[(j >> 1)*(2*NN) + n*2 + (j & 1)] = a;
    g_P1t[(j >> 1)*(2*NN) + n*2 + (j & 1)] = b;
    g_acc1[gid] = 0.0f;
    g_acc2[gid] = 0.0f;
    if (gid < 160) g_aggsum[gid] = 0.0f;
}

// ---------------- edge phase: symmetric pair tiles, uniform cost ----------------
template <int L>
__device__ __forceinline__ void edge_phase(const float* __restrict__ nuclei, char* smU)
{
    ull (*smStage)[32][9] = reinterpret_cast<ull (*)[32][9]>(smU);
    const ull* bt = reinterpret_cast<const ull*>((L == 0) ? g_B1t : g_B2t);
    const ull* pt = reinterpret_cast<const ull*>((L == 0) ? g_P1t : g_P2t);
    float*   accO = (L == 0) ? g_acc1 : g_acc2;
    const ulonglong2* w4 = reinterpret_cast<const ulonglong2*>(&cWe[L][0]);

    int tile = blockIdx.x >> 1, sub = blockIdx.x & 1;
    int tI = 0, rem = tile;
    while (rem >= NT - tI) { rem -= NT - tI; tI++; }
    const int tJ = tI + rem;
    const bool diag = (tI == tJ);

    const int wid = threadIdx.x >> 5, lane = threadIdx.x & 31;
    const int j = tJ*32 + lane;
    const float jx = __ldg(&nuclei[j*3 + 0]);
    const float jy = __ldg(&nuclei[j*3 + 1]);
    const float jz = __ldg(&nuclei[j*3 + 2]);
    const int fidx = ((lane >> 4) & 1)*8 + ((lane >> 3) & 1)*4
                   + ((lane >> 2) & 1)*2 + ((lane >> 1) & 1);

    #pragma unroll
    for (int P = 0; P < 2; P++) {
        ull colsum[8];
        #pragma unroll
        for (int u = 0; u < 8; u++) colsum[u] = 0ULL;

        #pragma unroll
        for (int ii = 0; ii < 2; ii++) {
            const int i = tI*32 + sub*16 + wid*2 + ii;
            float dx = jx - __ldg(&nuclei[i*3 + 0]);
            float dy = jy - __ldg(&nuclei[i*3 + 1]);
            float dz = jz - __ldg(&nuclei[i*3 + 2]);
            float d2 = fmaf(dx, dx, fmaf(dy, dy, dz*dz));
            // diag tiles: only i<j pairs live (both directions); off-diag: all pairs
            float mf = diag ? ((i < j) ? 1.0f : 0.0f) : 1.0f;
            d2 = (i == j) ? 1.0f : d2;
            float rsq = rsqrtf(d2);
            float si, co;
            __sincosf(d2 * rsq * 0.31415926535897931f, &si, &co);
            float twoc = co + co;

            ull acc[8];
            #pragma unroll
            for (int u = 0; u < 8; u++) acc[u] = 0ULL;
            float sp = 0.0f, sc = si;
            #pragma unroll
            for (int k = 0; k < 32; k++) {
                ulonglong2 wa = w4[k*8 + P*4 + 0];
                ulonglong2 wb = w4[k*8 + P*4 + 1];
                ulonglong2 wc = w4[k*8 + P*4 + 2];
                ulonglong2 wd = w4[k*8 + P*4 + 3];
                ull s2 = pk2(sc, sc);
                acc[0] = fma2(s2, wa.x, acc[0]); acc[1] = fma2(s2, wa.y, acc[1]);
                acc[2] = fma2(s2, wb.x, acc[2]); acc[3] = fma2(s2, wb.y, acc[3]);
                acc[4] = fma2(s2, wc.x, acc[4]); acc[5] = fma2(s2, wc.y, acc[5]);
                acc[6] = fma2(s2, wd.x, acc[6]); acc[7] = fma2(s2, wd.y, acc[7]);
                float sn = fmaf(twoc, sc, -sp); sp = sc; sc = sn;
            }
            float pf = 0.44721359549995794f * rsq;
            ull pref2 = pk2(pf, pf);

            // forward: sender i -> acc[i]
            float fs[16];
            #pragma unroll
            for (int u = 0; u < 8; u++) {
                ull bi = bt[(P*8 + u)*NN + i];   // uniform (L1)
                ull pj = pt[(P*8 + u)*NN + j];   // coalesced (L1)
                ull h2 = fma2(pref2, acc[u], add2(bi, pj));
                float hl, hg; upk2(h2, hl, hg);
                fs[2*u]   = silu_t(hl) * mf;
                fs[2*u+1] = silu_t(hg) * mf;
            }
            // transpose-reduce (16 shfls), even lanes hold one feature each
            float v8[8];
            #pragma unroll
            for (int f = 0; f < 8; f++) {
                float keep = (lane & 16) ? fs[f+8] : fs[f];
                float send = (lane & 16) ? fs[f]   : fs[f+8];
                v8[f] = keep + __shfl_xor_sync(0xffffffffu, send, 16);
            }
            float v4[4];
            #pragma unroll
            for (int f = 0; f < 4; f++) {
                float keep = (lane & 8) ? v8[f+4] : v8[f];
                float send = (lane & 8) ? v8[f]   : v8[f+4];
                v4[f] = keep + __shfl_xor_sync(0xffffffffu, send, 8);
            }
            float v2[2];
            #pragma unroll
            for (int f = 0; f < 2; f++) {
                float k2 = (lane & 4) ? v4[f+2] : v4[f];
                float s2 = (lane & 4) ? v4[f]   : v4[f+2];
                v2[f] = k2 + __shfl_xor_sync(0xffffffffu, s2, 4);
            }
            float k1 = (lane & 2) ? v2[1] : v2[0];
            float s1 = (lane & 2) ? v2[0] : v2[1];
            float v1 = k1 + __shfl_xor_sync(0xffffffffu, s1, 2);
            float v0 = v1 + __shfl_xor_sync(0xffffffffu, v1, 1);
            if (!(lane & 1))
                atomicAdd(&accO[i*32 + P*16 + fidx], v0);

            // backward: sender j -> acc[j] (masked identically)
            {
                ull m2 = pk2(mf, mf);
                #pragma unroll
                for (int u = 0; u < 8; u++) {
                    ull bj = bt[(P*8 + u)*NN + j];
                    ull pi = pt[(P*8 + u)*NN + i];
                    ull g2 = fma2(pref2, acc[u], add2(bj, pi));
                    float gl, gg; upk2(g2, gl, gg);
                    colsum[u] = fma2(pk2(silu_t(gl), silu_t(gg)), m2, colsum[u]);
                }
            }
        }

        #pragma unroll
        for (int u = 0; u < 8; u++) smStage[wid][lane][u] = colsum[u];
        __syncthreads();
        {
            int jl = threadIdx.x >> 3, u = threadIdx.x & 7;
            ull a = smStage[0][jl][u];
            #pragma unroll
            for (int w = 1; w < 8; w++) a = add2(a, smStage[w][jl][u]);
            float lo, hi; upk2(a, lo, hi);
            atomicAdd(&accO[(tJ*32 + jl)*32 + P*16 + 2*u],     lo);
            atomicAdd(&accO[(tJ*32 + jl)*32 + P*16 + 2*u + 1], hi);
        }
        __syncthreads();
    }
}

#define NBAR(id) asm volatile("bar.sync %0, 64;" :: "r"(id) : "memory")

// ---------------- node1 phase: 4 nodes per block, 64-thread groups ----------------
__device__ __forceinline__ void node1_phase(char* smU,
    const float* __restrict__ mp1_w1, const float* __restrict__ mp1_b1,
    const float* __restrict__ up1_w0, const float* __restrict__ up1_b0,
    const float* __restrict__ up1_w1, const float* __restrict__ up1_b1,
    const float* __restrict__ mp2_w0, const float* __restrict__ mp2_b0)
{
    const int g = threadIdx.x >> 6, t = threadIdx.x & 63;
    const int n = blockIdx.x*4 + g;
    if (n >= NN) return;
    float* S = reinterpret_cast<float*>(smU) + g*256;
    float* in64 = S; float* h = S + 64; float* e1 = S + 128; float* m = S + 192;
    const int bid = g + 1;
    if (t < 32) {
        in64[t] = g_embed0[n*32 + t];
        m[t] = g_acc1[n*32 + t] * (1.0f / CNT);
    }
    NBAR(bid);
    if (t < 32) {
        float a = __ldg(&mp1_b1[t]);
        #pragma unroll
        for (int k = 0; k < 32; k++) a = fmaf(m[k], __ldg(&mp1_w1[k*32 + t]), a);
        in64[32 + t] = a;
    }
    NBAR(bid);
    {
        float a = __ldg(&up1_b0[t]);
        #pragma unroll 8
        for (int k = 0; k < 64; k++) a = fmaf(in64[k], __ldg(&up1_w0[k*64 + t]), a);
        h[t] = silu_f(a);
    }
    NBAR(bid);
    {
        float a = __ldg(&up1_b1[t]);
        #pragma unroll 8
        for (int k = 0; k < 64; k++) a = fmaf(h[k], __ldg(&up1_w1[k*64 + t]), a);
        e1[t] = a;
        g_e1[n*64 + t] = a;
    }
    NBAR(bid);
    if (t < 32) {
        float a = __ldg(&mp2_b0[t]), b = 0.0f;
        #pragma unroll 8
        for (int k = 0; k < 64; k++) {
            float e = e1[k];
            a = fmaf(e, __ldg(&mp2_w0[k*32 + t]),        a);
            b = fmaf(e, __ldg(&mp2_w0[(64 + k)*32 + t]), b);
        }
        g_B2t[(t >> 1)*(2*NN) + n*2 + (t & 1)] = a;
        g_P2t[(t >> 1)*(2*NN) + n*2 + (t & 1)] = b;
    }
}

// ---------------- node2 phase ----------------
__device__ __forceinline__ void node2_phase(char* smU,
    const int*   __restrict__ charges,
    const float* __restrict__ mp2_w1, const float* __restrict__ mp2_b1,
    const float* __restrict__ up2_w0, const float* __restrict__ up2_b0,
    const float* __restrict__ up2_w1, const float* __restrict__ up2_b1,
    const float* __restrict__ no_w0,  const float* __restrict__ no_b0,
    const float* __restrict__ no_w1,  const float* __restrict__ no_embed,
    float* __restrict__ out)
{
    const int g = threadIdx.x >> 6, t = threadIdx.x & 63;
    const int n = blockIdx.x*4 + g;
    if (n >= NN) return;
    float* S = reinterpret_cast<float*>(smU) + g*368;
    float* agg = S; float* in96 = S + 160; float* h = S + 256;
    float* m = S + 320; float* t3 = S + 352;
    const int bid = g + 1;
    if (t < 32) {
        m[t] = g_acc2[n*32 + t] * (1.0f / CNT);
        agg[t] = g_embed0[n*32 + t];
    }
    float e1v = g_e1[n*64 + t];
    agg[32 + t] = e1v;
    in96[t] = e1v;
    NBAR(bid);
    if (t < 32) {
        float a = __ldg(&mp2_b1[t]);
        #pragma unroll
        for (int k = 0; k < 32; k++) a = fmaf(m[k], __ldg(&mp2_w1[k*32 + t]), a);
        in96[64 + t] = a;
    }
    NBAR(bid);
    {
        float a = __ldg(&up2_b0[t]);
        #pragma unroll 8
        for (int k = 0; k < 96; k++) a = fmaf(in96[k], __ldg(&up2_w0[k*64 + t]), a);
        h[t] = silu_f(a);
    }
    NBAR(bid);
    {
        float a = __ldg(&up2_b1[t]) + e1v;
        #pragma unroll 8
        for (int k = 0; k < 64; k++) a = fmaf(h[k], __ldg(&up2_w1[k*64 + t]), a);
        agg[96 + t] = a;
    }
    NBAR(bid);
    if (t < 3) {
        float a = __ldg(&no_b0[t]);
        for (int k = 0; k < 160; k++) a = fmaf(agg[k], __ldg(&no_w0[k*3 + t]), a);
        t3[t] = silu_f(a);
    }
    for (int i = t; i < 160; i += 64) atomicAdd(&g_aggsum[i], agg[i]);
    NBAR(bid);
    if (t < 3) {
        int c = __ldg(&charges[n]);
        float o = __ldg(&no_embed[c*3 + t]);
        #pragma unroll
        for (int k = 0; k < 3; k++) o = fmaf(t3[k], __ldg(&no_w1[k*3 + t]), o);
        out[n*3 + t] = o;
    }
}

// ---------------- global phase (block 0 only) ----------------
__device__ __forceinline__ void global_phase(char* smU,
    const float* __restrict__ go_w0, const float* __restrict__ go_b0,
    const float* __restrict__ go_w1, const float* __restrict__ go_b1,
    float* __restrict__ out)
{
    float* red = reinterpret_cast<float*>(smU);
    int t = threadIdx.x;
    float p = 0.0f;
    if (t < 160) p = g_aggsum[t] * __ldg(&go_w0[t]);
    red[t] = p;
    __syncthreads();
    for (int s = 128; s > 0; s >>= 1) {
        if (t < s) red[t] += red[t + s];
        __syncthreads();
    }
    if (t == 0) {
        float hh = silu_f(red[0] * (1.0f / (float)NN) + __ldg(&go_b0[0]));
        out[NN*3] = fmaf(hh, __ldg(&go_w1[0]), __ldg(&go_b1[0]));
    }
}

// ---------------- persistent mega kernel ----------------
__global__ __launch_bounds__(TPB, 4) void mega_kernel(
    const float* nuclei, const int* charges, const float* embed_table,
    const float* mp1_w0, const float* mp1_b0, const float* mp1_w1, const float* mp1_b1,
    const float* up1_w0, const float* up1_b0, const float* up1_w1, const float* up1_b1,
    const float* mp2_w0, const float* mp2_b0, const float* mp2_w1, const float* mp2_b1,
    const float* up2_w0, const float* up2_b0, const float* up2_w1, const float* up2_b1,
    const float* no_w0, const float* no_b0, const float* no_w1, const float* no_emb,
    const float* go_w0, const float* go_b0, const float* go_w1, const float* go_b1,
    float* out)
{
    __shared__ __align__(16) char smU[18432];
    prep_phase(embed_table, charges, mp1_w0, mp1_b0);
    gridsync(1*GRID);
    edge_phase<0>(nuclei, smU);
    gridsync(2*GRID);
    node1_phase(smU, mp1_w1, mp1_b1, up1_w0, up1_b0, up1_w1, up1_b1, mp2_w0, mp2_b0);
    gridsync(3*GRID);
    edge_phase<1>(nuclei, smU);
    gridsync(4*GRID);
    node2_phase(smU, charges, mp2_w1, mp2_b1, up2_w0, up2_b0, up2_w1, up2_b1,
                no_w0, no_b0, no_w1, no_emb, out);
    gridsync(5*GRID);
    if (blockIdx.x == 0) {
        global_phase(smU, go_w0, go_b0, go_w1, go_b1, out);
        __syncthreads();
        if (threadIdx.x == 0) atomicExch(&g_bar, 0u);   // reset for next replay
    }
}

// ---------------- fallback wrappers (non-co-resident devices) ----------------
__global__ __launch_bounds__(TPB, 4) void prep_k(const float* et, const int* ch,
                                                 const float* w0, const float* b0)
{ prep_phase(et, ch, w0, b0); }

template <int L>
__global__ __launch_bounds__(TPB, 4) void edge_k(const float* nuclei)
{ __shared__ __align__(16) char smU[18432]; edge_phase<L>(nuclei, smU); }

__global__ __launch_bounds__(TPB, 4) void node1_k(
    const float* a, const float* b, const float* c, const float* d,
    const float* e, const float* f, const float* g, const float* h)
{ __shared__ __align__(16) char smU[4096]; node1_phase(smU, a, b, c, d, e, f, g, h); }

__global__ __launch_bounds__(TPB, 4) void node2_k(
    const int* ch, const float* a, const float* b, const float* c, const float* d,
    const float* e, const float* f, const float* g, const float* h,
    const float* i, const float* j, float* out)
{ __shared__ __align__(16) char smU[5888]; node2_phase(smU, ch, a, b, c, d, e, f, g, h, i, j, out); }

__global__ void global_k(const float* a, const float* b, const float* c, const float* d, float* out)
{ __shared__ __align__(16) char smU[1024]; global_phase(smU, a, b, c, d, out); }

// ---------------- host-side launch ----------------
extern "C" void kernel_launch(void* const* d_in, const int* in_sizes, int n_in,
                              void* d_out, int out_size)
{
    const float* nuclei      = (const float*)d_in[0];
    const int*   charges     = (const int*)  d_in[1];
    const float* embed_table = (const float*)d_in[3];
    const float* mp1_w0 = (const float*)d_in[4];
    const float* mp1_b0 = (const float*)d_in[5];
    const float* mp1_w1 = (const float*)d_in[6];
    const float* mp1_b1 = (const float*)d_in[7];
    const float* up1_w0 = (const float*)d_in[8];
    const float* up1_b0 = (const float*)d_in[9];
    const float* up1_w1 = (const float*)d_in[10];
    const float* up1_b1 = (const float*)d_in[11];
    const float* mp2_w0 = (const float*)d_in[12];
    const float* mp2_b0 = (const float*)d_in[13];
    const float* mp2_w1 = (const float*)d_in[14];
    const float* mp2_b1 = (const float*)d_in[15];
    const float* up2_w0 = (const float*)d_in[16];
    const float* up2_b0 = (const float*)d_in[17];
    const float* up2_w1 = (const float*)d_in[18];
    const float* up2_b1 = (const float*)d_in[19];
    const float* no_w0  = (const float*)d_in[20];
    const float* no_b0  = (const float*)d_in[21];
    const float* no_w1  = (const float*)d_in[22];
    const float* no_emb = (const float*)d_in[23];
    const float* go_w0  = (const float*)d_in[24];
    const float* go_b0  = (const float*)d_in[25];
    const float* go_w1  = (const float*)d_in[26];
    const float* go_b1  = (const float*)d_in[27];
    float* out = (float*)d_out;

    void* cwAddr = nullptr;
    cudaGetSymbolAddress(&cwAddr, cWe);
    cudaMemcpyAsync((char*)cwAddr,        mp1_w0 + 64*32,  4096, cudaMemcpyDeviceToDevice);
    cudaMemcpyAsync((char*)cwAddr + 4096, mp2_w0 + 128*32, 4096, cudaMemcpyDeviceToDevice);

    int dev = 0, sms = 0;
    cudaGetDevice(&dev);
    cudaDeviceGetAttribute(&sms, cudaDevAttrMultiProcessorCount, dev);

    if (sms * 4 >= GRID) {
        mega_kernel<<<GRID, TPB>>>(nuclei, charges, embed_table,
            mp1_w0, mp1_b0, mp1_w1, mp1_b1, up1_w0, up1_b0, up1_w1, up1_b1,
            mp2_w0, mp2_b0, mp2_w1, mp2_b1, up2_w0, up2_b0, up2_w1, up2_b1,
            no_w0, no_b0, no_w1, no_emb, go_w0, go_b0, go_w1, go_b1, out);
    } else {
        prep_k<<<96, TPB>>>(embed_table, charges, mp1_w0, mp1_b0);
        edge_k<0><<<GRID, TPB>>>(nuclei);
        node1_k<<<192, TPB>>>(mp1_w1, mp1_b1, up1_w0, up1_b0, up1_w1, up1_b1, mp2_w0, mp2_b0);
        edge_k<1><<<GRID, TPB>>>(nuclei);
        node2_k<<<192, TPB>>>(charges, mp2_w1, mp2_b1, up2_w0, up2_b0, up2_w1, up2_b1,
                              no_w0, no_b0, no_w1, no_emb, out);
        global_k<<<1, TPB>>>(go_w0, go_b0, go_w1, go_b1, out);
    }
}